// round 12
// baseline (speedup 1.0000x reference)
#include <cuda_runtime.h>
#include <cstdint>

typedef unsigned long long ull;
typedef unsigned int uint;

constexpr int BH  = 8;
constexpr int T   = 512;
constexpr int D   = 64;
constexpr int HID = 128;
constexpr int NP  = HID / 2;   // 64 channel pairs

// pair-major scratch: [bh][pair][T] as 64-bit channel pairs, |w2| folded, b1 folded into k
__device__ ull  g_qsp[BH * NP * T];   // 2 MB
__device__ ull  g_ksp[BH * NP * T];   // 2 MB
__device__ uint g_bar;                // monotonic ticket counter (never reset)

// smem: phase A needs 49.4KB; phase B needs 164.4KB. Take max.
constexpr int SMF_BYTES = NP * 64 * 8 + NP * 256 * 8 + NP * 8;   // 164352

__global__ __launch_bounds__(1024, 1) void kfused(
    const float* __restrict__ q, const float* __restrict__ k,
    const float* __restrict__ W1, const float* __restrict__ b1,
    const float* __restrict__ W2, const float* __restrict__ b2,
    float* __restrict__ out)
{
    extern __shared__ char sm[];
    int tid = threadIdx.x;
    int bx  = blockIdx.x;

    // ================= Phase A: projection slice (k1 shape: 256 active threads) =================
    {
        ull*   sWp = (ull*)sm;               // [D][NP] 32KB
        float* sR  = (float*)(sm + 32768);   // [64][68]
        ull*   sT  = (ull*)sm;               // [64][65] (aliased after sync)

        int r0  = (bx >> 4) * 64;
        int bh  = (bx >> 1) & 7;
        int isk = bx & 1;

        const float* src  = isk ? k : q;
        const float* wsrc = W1 + (isk ? D * HID : 0);

        for (int idx = tid; idx < D * HID / 4; idx += 1024) {
            int d = idx >> 5, g = idx & 31;
            *(float4*)&sWp[d * NP + 2 * g] = *(const float4*)&wsrc[d * HID + g * 4];
        }
        for (int idx = tid; idx < 64 * D / 4; idx += 1024) {
            int r = idx >> 4, c = idx & 15;
            *(float4*)&sR[r * 68 + c * 4] = *(const float4*)&src[(bh * T + r0 + r) * D + c * 4];
        }
        __syncthreads();

        ull accA[4][4];
        float gg[8], bb[8];
        int ti = tid >> 4;      // 16 groups x 4 rows (active: tid < 256)
        int tc = tid & 15;      // pairs {tc, tc+16, tc+32, tc+48}

        if (tid < 256) {
            #pragma unroll
            for (int a = 0; a < 4; a++)
                #pragma unroll
                for (int b = 0; b < 4; b++) accA[a][b] = 0ull;

            #pragma unroll 2
            for (int d = 0; d < D; d++) {
                ull w0 = sWp[d * NP + tc];
                ull w1 = sWp[d * NP + tc + 16];
                ull w2 = sWp[d * NP + tc + 32];
                ull w3 = sWp[d * NP + tc + 48];
                #pragma unroll
                for (int ii = 0; ii < 4; ii++) {
                    float a = sR[(ti * 4 + ii) * 68 + d];
                    ull ap; asm("mov.b64 %0, {%1,%1};" : "=l"(ap) : "f"(a));
                    asm("fma.rn.f32x2 %0, %1, %2, %0;" : "+l"(accA[ii][0]) : "l"(ap), "l"(w0));
                    asm("fma.rn.f32x2 %0, %1, %2, %0;" : "+l"(accA[ii][1]) : "l"(ap), "l"(w1));
                    asm("fma.rn.f32x2 %0, %1, %2, %0;" : "+l"(accA[ii][2]) : "l"(ap), "l"(w2));
                    asm("fma.rn.f32x2 %0, %1, %2, %0;" : "+l"(accA[ii][3]) : "l"(ap), "l"(w3));
                }
            }

            // per-channel params: gg = |w2_c|, bb = b1 (k side only); channels 2*(tc+16m)+e
            #pragma unroll
            for (int m = 0; m < 4; m++)
                #pragma unroll
                for (int e = 0; e < 2; e++) {
                    int ch = 2 * (tc + 16 * m) + e;
                    gg[2 * m + e] = fabsf(W2[ch]);
                    bb[2 * m + e] = isk ? b1[ch] : 0.0f;
                }
        }

        __syncthreads();   // sWp/sR dead; sT may alias now

        if (tid < 256) {
            #pragma unroll
            for (int ii = 0; ii < 4; ii++) {
                #pragma unroll
                for (int m = 0; m < 4; m++) {
                    float lo = __uint_as_float((uint)(accA[ii][m] & 0xffffffffu));
                    float hi = __uint_as_float((uint)(accA[ii][m] >> 32));
                    float o0 = gg[2 * m]     * (lo + bb[2 * m]);
                    float o1 = gg[2 * m + 1] * (hi + bb[2 * m + 1]);
                    ull pr = (ull)__float_as_uint(o0) | ((ull)__float_as_uint(o1) << 32);
                    sT[(ti * 4 + ii) * 65 + tc + 16 * m] = pr;
                }
            }
        }
        __syncthreads();

        // coalesced pair-major writeout (all 1024 threads)
        ull* dst = (isk ? g_ksp : g_qsp) + (size_t)bh * NP * T;
        for (int idx = tid; idx < 64 * NP; idx += 1024) {
            int r = idx & 63, p = idx >> 6;
            dst[p * T + r0 + r] = sT[r * 65 + p];
        }
    }

    // ================= device-wide ticket barrier (all 128 CTAs resident) =================
    __threadfence();       // make this thread's g_qsp/g_ksp stores visible GPU-wide
    __syncthreads();       // all threads of CTA fenced before the CTA arrives
    if (tid == 0) {
        uint my = atomicAdd(&g_bar, 1u);
        uint target = (my & ~127u) + 128u;   // end of this replay's round (monotonic, replay-safe)
        while ((int)(*(volatile uint*)&g_bar - target) < 0) {}
        __threadfence();
    }
    __syncthreads();

    // ================= Phase B: pairwise relu main (R8 k3 body) =================
    {
        ull* sq  = (ull*)sm;             // [p][64 rows]
        ull* sk  = sq + NP * 64;         // [p][256 cols]
        ull* ssg = sk + NP * 256;        // [64] packed (+-1.0f, +-1.0f)

        int bh = bx >> 4;
        int it = (bx >> 1) & 7;
        int jt = bx & 1;
        int i0 = it * 64, j0 = jt * 256;

        const ull* gq = g_qsp + (size_t)bh * NP * T;
        const ull* gk = g_ksp + (size_t)bh * NP * T;

        for (int idx = tid; idx < NP * 64; idx += 1024) {
            int p = idx >> 6, r = idx & 63;
            sq[idx] = gq[p * T + i0 + r];
        }
        for (int idx = tid; idx < NP * 256; idx += 1024) {
            int p = idx >> 8, r = idx & 255;
            sk[idx] = gk[p * T + j0 + r];
        }
        if (tid < NP) {
            uint s0 = 0x3F800000u | (__float_as_uint(W2[2 * tid])     & 0x80000000u);
            uint s1 = 0x3F800000u | (__float_as_uint(W2[2 * tid + 1]) & 0x80000000u);
            ssg[tid] = (ull)s0 | ((ull)s1 << 32);
        }
        __syncthreads();

        int warp = tid >> 5, lane = tid & 31;
        int wi = warp >> 3, wj = warp & 7;   // 4x8 warps: warp tile 16x32
        int li = lane >> 3, lj = lane & 7;   // lanes: 4 row-groups x 8 col-groups

        const ull* qb = sq + wi * 16 + 4 * li;   // rows 4li..4li+3, + 64p
        const ull* kb = sk + wj * 32 + 4 * lj;   // cols 4lj..4lj+3, + 256p

        ull acc[4][4];
        #pragma unroll
        for (int r = 0; r < 4; r++)
            #pragma unroll
            for (int s = 0; s < 4; s++) acc[r][s] = 0ull;

        #pragma unroll 1
        for (int p = 0; p < NP; p++) {
            ulonglong2 qv01 = *(const ulonglong2*)(qb + p * 64);
            ulonglong2 qv23 = *(const ulonglong2*)(qb + p * 64 + 2);
            ulonglong2 kv01 = *(const ulonglong2*)(kb + p * 256);
            ulonglong2 kv23 = *(const ulonglong2*)(kb + p * 256 + 2);
            ull qv[4] = { qv01.x, qv01.y, qv23.x, qv23.y };
            ull kv[4] = { kv01.x, kv01.y, kv23.x, kv23.y };
            ull sg = ssg[p];
            #pragma unroll
            for (int r = 0; r < 4; r++)
                #pragma unroll
                for (int s = 0; s < 4; s++) {
                    // u = q+k (packed); relu halves (FMNMX, alu pipe); acc += u * (+-1) (packed)
                    asm("{\n\t"
                        ".reg .b64 t;\n\t"
                        ".reg .f32 lo, hi;\n\t"
                        "add.rn.f32x2 t, %1, %2;\n\t"
                        "mov.b64 {lo, hi}, t;\n\t"
                        "max.f32 lo, lo, 0f00000000;\n\t"
                        "max.f32 hi, hi, 0f00000000;\n\t"
                        "mov.b64 t, {lo, hi};\n\t"
                        "fma.rn.f32x2 %0, t, %3, %0;\n\t"
                        "}"
                        : "+l"(acc[r][s]) : "l"(qv[r]), "l"(kv[s]), "l"(sg));
                }
        }

        float b2v = b2[0];
        // rows: i0 + wi*16 + 4*li + r; cols: j0 + wj*32 + 4*lj + s (consecutive -> STG.128)
        float* ob = out + (size_t)(bh * T + i0 + wi * 16 + 4 * li) * T + j0 + wj * 32 + 4 * lj;
        #pragma unroll
        for (int r = 0; r < 4; r++) {
            float4 v;
            float* vp = (float*)&v;
            #pragma unroll
            for (int s = 0; s < 4; s++) {
                float lo = __uint_as_float((uint)(acc[r][s] & 0xffffffffu));
                float hi = __uint_as_float((uint)(acc[r][s] >> 32));
                vp[s] = lo + hi + b2v;
            }
            *(float4*)(ob + (size_t)r * T) = v;
        }
    }
}

// ---------------- launch ----------------
extern "C" void kernel_launch(void* const* d_in, const int* in_sizes, int n_in,
                              void* d_out, int out_size) {
    const float* q  = (const float*)d_in[0];
    const float* k  = (const float*)d_in[1];
    const float* W1 = (const float*)d_in[2];
    const float* b1 = (const float*)d_in[3];
    const float* W2 = (const float*)d_in[4];
    const float* b2 = (const float*)d_in[5];
    float* out = (float*)d_out;

    cudaFuncSetAttribute(kfused, cudaFuncAttributeMaxDynamicSharedMemorySize, SMF_BYTES);

    kfused<<<128, 1024, SMF_BYTES>>>(q, k, W1, b1, W2, b2, out);
}

// round 13
// speedup vs baseline: 1.0410x; 1.0410x over previous
#include <cuda_runtime.h>
#include <cstdint>

typedef unsigned long long ull;
typedef unsigned int uint;

constexpr int BH  = 8;
constexpr int T   = 512;
constexpr int D   = 64;
constexpr int HID = 128;
constexpr int NP  = HID / 2;   // 64 channel pairs

// pair-major scratch: [bh][pair][T] as 64-bit channel pairs, |w2| folded, b1 folded into k
__device__ ull g_qsp[BH * NP * T];   // 2 MB
__device__ ull g_ksp[BH * NP * T];   // 2 MB

// ---------------- K1: projections (|w2| and b1 folded) + pair-major transpose ----------------
// 32 rows per CTA, 256 CTAs for latency overlap.
// smem: sWp [64][64] ull (32KB) | sR [32][68] float (8.7KB); sT [32][65] ull aliases at 0.
constexpr int SM1_BYTES = 32768 + 32 * 68 * 4;   // 41472

__global__ __launch_bounds__(256) void k1_proj(
    const float* __restrict__ q, const float* __restrict__ k,
    const float* __restrict__ W1, const float* __restrict__ b1,
    const float* __restrict__ W2)
{
    extern __shared__ char sm1[];
    ull*   sWp = (ull*)sm1;               // [D][NP]
    float* sR  = (float*)(sm1 + 32768);   // [32][68]
    ull*   sT  = (ull*)sm1;               // [32][65] (aliased after sync)

    int tid = threadIdx.x;
    int bh  = blockIdx.y;
    int r0  = blockIdx.x * 32;
    int isk = blockIdx.z;

    const float* src  = isk ? k : q;
    const float* wsrc = W1 + (isk ? D * HID : 0);

    for (int idx = tid; idx < D * HID / 4; idx += 256) {
        int d = idx >> 5, g = idx & 31;
        *(float4*)&sWp[d * NP + 2 * g] = *(const float4*)&wsrc[d * HID + g * 4];
    }
    for (int idx = tid; idx < 32 * D / 4; idx += 256) {
        int r = idx >> 4, c = idx & 15;
        *(float4*)&sR[r * 68 + c * 4] = *(const float4*)&src[(bh * T + r0 + r) * D + c * 4];
    }
    __syncthreads();

    int ti = tid >> 4;      // 16 groups x 2 rows
    int tc = tid & 15;      // pairs {tc, tc+16, tc+32, tc+48}

    ull acc[2][4];
    #pragma unroll
    for (int a = 0; a < 2; a++)
        #pragma unroll
        for (int b = 0; b < 4; b++) acc[a][b] = 0ull;

    #pragma unroll 4
    for (int d = 0; d < D; d++) {
        ull w0 = sWp[d * NP + tc];
        ull w1 = sWp[d * NP + tc + 16];
        ull w2 = sWp[d * NP + tc + 32];
        ull w3 = sWp[d * NP + tc + 48];
        #pragma unroll
        for (int ii = 0; ii < 2; ii++) {
            float a = sR[(ti * 2 + ii) * 68 + d];
            ull ap; asm("mov.b64 %0, {%1,%1};" : "=l"(ap) : "f"(a));
            asm("fma.rn.f32x2 %0, %1, %2, %0;" : "+l"(acc[ii][0]) : "l"(ap), "l"(w0));
            asm("fma.rn.f32x2 %0, %1, %2, %0;" : "+l"(acc[ii][1]) : "l"(ap), "l"(w1));
            asm("fma.rn.f32x2 %0, %1, %2, %0;" : "+l"(acc[ii][2]) : "l"(ap), "l"(w2));
            asm("fma.rn.f32x2 %0, %1, %2, %0;" : "+l"(acc[ii][3]) : "l"(ap), "l"(w3));
        }
    }

    // per-channel params: gg = |w2_c|, bb = b1 (k side only); channels 2*(tc+16m)+e
    float gg[8], bb[8];
    #pragma unroll
    for (int m = 0; m < 4; m++)
        #pragma unroll
        for (int e = 0; e < 2; e++) {
            int ch = 2 * (tc + 16 * m) + e;
            gg[2 * m + e] = fabsf(W2[ch]);
            bb[2 * m + e] = isk ? b1[ch] : 0.0f;
        }

    __syncthreads();   // sW/sR dead; sT may alias now

    #pragma unroll
    for (int ii = 0; ii < 2; ii++) {
        #pragma unroll
        for (int m = 0; m < 4; m++) {
            float lo = __uint_as_float((uint)(acc[ii][m] & 0xffffffffu));
            float hi = __uint_as_float((uint)(acc[ii][m] >> 32));
            float o0 = gg[2 * m]     * (lo + bb[2 * m]);
            float o1 = gg[2 * m + 1] * (hi + bb[2 * m + 1]);
            ull pr = (ull)__float_as_uint(o0) | ((ull)__float_as_uint(o1) << 32);
            sT[(ti * 2 + ii) * 65 + tc + 16 * m] = pr;
        }
    }
    __syncthreads();

    // coalesced pair-major writeout (32 rows x 64 pairs)
    ull* dst = (isk ? g_ksp : g_qsp) + (size_t)bh * NP * T;
    for (int idx = tid; idx < 32 * NP; idx += 256) {
        int r = idx & 31, p = idx >> 5;
        dst[p * T + r0 + r] = sT[r * 65 + p];
    }
}

// ---------------- K3: pairwise relu main kernel (R8 proven: 1024 thr, 64x256 tile) ----------------
constexpr int SM3_BYTES = NP * 64 * 8 + NP * 256 * 8 + NP * 8;   // 164352

__global__ __launch_bounds__(1024, 1) void k3_main(
    const float* __restrict__ W2, const float* __restrict__ b2,
    float* __restrict__ out)
{
    extern __shared__ ull sm3[];
    ull* sq  = sm3;              // [p][64 rows]
    ull* sk  = sq + NP * 64;     // [p][256 cols]
    ull* ssg = sk + NP * 256;    // [64] packed (+-1.0f, +-1.0f)

    int tid = threadIdx.x;
    int bx  = blockIdx.x;
    int bh  = bx >> 4;
    int it  = (bx >> 1) & 7;
    int jt  = bx & 1;
    int i0  = it * 64, j0 = jt * 256;

    const ull* gq = g_qsp + (size_t)bh * NP * T;
    const ull* gk = g_ksp + (size_t)bh * NP * T;

    for (int idx = tid; idx < NP * 64; idx += 1024) {
        int p = idx >> 6, r = idx & 63;
        sq[idx] = gq[p * T + i0 + r];
    }
    for (int idx = tid; idx < NP * 256; idx += 1024) {
        int p = idx >> 8, r = idx & 255;
        sk[idx] = gk[p * T + j0 + r];
    }
    if (tid < NP) {
        uint s0 = 0x3F800000u | (__float_as_uint(W2[2 * tid])     & 0x80000000u);
        uint s1 = 0x3F800000u | (__float_as_uint(W2[2 * tid + 1]) & 0x80000000u);
        ssg[tid] = (ull)s0 | ((ull)s1 << 32);
    }
    __syncthreads();

    int warp = tid >> 5, lane = tid & 31;
    int wi = warp >> 3, wj = warp & 7;   // 4x8 warps: warp tile 16x32
    int li = lane >> 3, lj = lane & 7;   // lanes: 4 row-groups x 8 col-groups

    const ull* qb = sq + wi * 16 + 4 * li;   // rows 4li..4li+3, + 64p
    const ull* kb = sk + wj * 32 + 4 * lj;   // cols 4lj..4lj+3, + 256p

    ull acc[4][4];
    #pragma unroll
    for (int r = 0; r < 4; r++)
        #pragma unroll
        for (int s = 0; s < 4; s++) acc[r][s] = 0ull;

    #pragma unroll 1
    for (int p = 0; p < NP; p++) {
        ulonglong2 qv01 = *(const ulonglong2*)(qb + p * 64);
        ulonglong2 qv23 = *(const ulonglong2*)(qb + p * 64 + 2);
        ulonglong2 kv01 = *(const ulonglong2*)(kb + p * 256);
        ulonglong2 kv23 = *(const ulonglong2*)(kb + p * 256 + 2);
        ull qv[4] = { qv01.x, qv01.y, qv23.x, qv23.y };
        ull kv[4] = { kv01.x, kv01.y, kv23.x, kv23.y };
        ull sg = ssg[p];
        #pragma unroll
        for (int r = 0; r < 4; r++)
            #pragma unroll
            for (int s = 0; s < 4; s++) {
                // u = q+k (packed); relu halves (FMNMX, alu pipe); acc += u * (+-1) (packed)
                asm("{\n\t"
                    ".reg .b64 t;\n\t"
                    ".reg .f32 lo, hi;\n\t"
                    "add.rn.f32x2 t, %1, %2;\n\t"
                    "mov.b64 {lo, hi}, t;\n\t"
                    "max.f32 lo, lo, 0f00000000;\n\t"
                    "max.f32 hi, hi, 0f00000000;\n\t"
                    "mov.b64 t, {lo, hi};\n\t"
                    "fma.rn.f32x2 %0, t, %3, %0;\n\t"
                    "}"
                    : "+l"(acc[r][s]) : "l"(qv[r]), "l"(kv[s]), "l"(sg));
            }
    }

    float b2v = b2[0];
    // rows: i0 + wi*16 + 4*li + r; cols: j0 + wj*32 + 4*lj + s (consecutive -> STG.128)
    float* ob = out + (size_t)(bh * T + i0 + wi * 16 + 4 * li) * T + j0 + wj * 32 + 4 * lj;
    #pragma unroll
    for (int r = 0; r < 4; r++) {
        float4 v;
        float* vp = (float*)&v;
        #pragma unroll
        for (int s = 0; s < 4; s++) {
            float lo = __uint_as_float((uint)(acc[r][s] & 0xffffffffu));
            float hi = __uint_as_float((uint)(acc[r][s] >> 32));
            vp[s] = lo + hi + b2v;
        }
        *(float4*)(ob + (size_t)r * T) = v;
    }
}

// ---------------- launch ----------------
extern "C" void kernel_launch(void* const* d_in, const int* in_sizes, int n_in,
                              void* d_out, int out_size) {
    const float* q  = (const float*)d_in[0];
    const float* k  = (const float*)d_in[1];
    const float* W1 = (const float*)d_in[2];
    const float* b1 = (const float*)d_in[3];
    const float* W2 = (const float*)d_in[4];
    const float* b2 = (const float*)d_in[5];
    float* out = (float*)d_out;

    cudaFuncSetAttribute(k1_proj, cudaFuncAttributeMaxDynamicSharedMemorySize, SM1_BYTES);
    cudaFuncSetAttribute(k3_main, cudaFuncAttributeMaxDynamicSharedMemorySize, SM3_BYTES);

    k1_proj<<<dim3(16, BH, 2), 256, SM1_BYTES>>>(q, k, W1, b1, W2);
    k3_main<<<128, 1024, SM3_BYTES>>>(W2, b2, out);
}

// round 14
// speedup vs baseline: 1.1303x; 1.0858x over previous
#include <cuda_runtime.h>
#include <cstdint>

typedef unsigned long long ull;
typedef unsigned int uint;

constexpr int BH  = 8;
constexpr int T   = 512;
constexpr int D   = 64;
constexpr int HID = 128;
constexpr int NP  = HID / 2;   // 64 channel pairs

// pair-major scratch: [bh][pair][T] as 64-bit channel pairs, |w2| folded, b1 folded into k
__device__ ull g_qsp[BH * NP * T];   // 2 MB
__device__ ull g_ksp[BH * NP * T];   // 2 MB

// ---------------- K1: projections (|w2| and b1 folded) + pair-major transpose ----------------
// R4-proven: 64 rows per CTA, grid (8, BH, 2), 256 threads.
// smem: sWp [64][64] ull (32KB) | sR [64][68] float (17.4KB); sT [64][65] ull aliases at 0.
constexpr int SM1_BYTES = 32768 + 64 * 68 * 4;   // 50176

__global__ __launch_bounds__(256) void k1_proj(
    const float* __restrict__ q, const float* __restrict__ k,
    const float* __restrict__ W1, const float* __restrict__ b1,
    const float* __restrict__ W2)
{
    extern __shared__ char sm1[];
    ull*   sWp = (ull*)sm1;               // [D][NP]
    float* sR  = (float*)(sm1 + 32768);   // [64][68]
    ull*   sT  = (ull*)sm1;               // [64][65] (aliased after sync)

    int tid = threadIdx.x;
    int bh  = blockIdx.y;
    int r0  = blockIdx.x * 64;
    int isk = blockIdx.z;

    const float* src  = isk ? k : q;
    const float* wsrc = W1 + (isk ? D * HID : 0);

    for (int idx = tid; idx < D * HID / 4; idx += 256) {
        int d = idx >> 5, g = idx & 31;
        *(float4*)&sWp[d * NP + 2 * g] = *(const float4*)&wsrc[d * HID + g * 4];
    }
    for (int idx = tid; idx < 64 * D / 4; idx += 256) {
        int r = idx >> 4, c = idx & 15;
        *(float4*)&sR[r * 68 + c * 4] = *(const float4*)&src[(bh * T + r0 + r) * D + c * 4];
    }
    __syncthreads();

    int ti = tid >> 4;      // 16 groups x 4 rows
    int tc = tid & 15;      // pairs {tc, tc+16, tc+32, tc+48}

    ull acc[4][4];
    #pragma unroll
    for (int a = 0; a < 4; a++)
        #pragma unroll
        for (int b = 0; b < 4; b++) acc[a][b] = 0ull;

    #pragma unroll 2
    for (int d = 0; d < D; d++) {
        ull w0 = sWp[d * NP + tc];
        ull w1 = sWp[d * NP + tc + 16];
        ull w2 = sWp[d * NP + tc + 32];
        ull w3 = sWp[d * NP + tc + 48];
        #pragma unroll
        for (int ii = 0; ii < 4; ii++) {
            float a = sR[(ti * 4 + ii) * 68 + d];
            ull ap; asm("mov.b64 %0, {%1,%1};" : "=l"(ap) : "f"(a));
            asm("fma.rn.f32x2 %0, %1, %2, %0;" : "+l"(acc[ii][0]) : "l"(ap), "l"(w0));
            asm("fma.rn.f32x2 %0, %1, %2, %0;" : "+l"(acc[ii][1]) : "l"(ap), "l"(w1));
            asm("fma.rn.f32x2 %0, %1, %2, %0;" : "+l"(acc[ii][2]) : "l"(ap), "l"(w2));
            asm("fma.rn.f32x2 %0, %1, %2, %0;" : "+l"(acc[ii][3]) : "l"(ap), "l"(w3));
        }
    }

    // per-channel params: gg = |w2_c|, bb = b1 (k side only); channels 2*(tc+16m)+e
    float gg[8], bb[8];
    #pragma unroll
    for (int m = 0; m < 4; m++)
        #pragma unroll
        for (int e = 0; e < 2; e++) {
            int ch = 2 * (tc + 16 * m) + e;
            gg[2 * m + e] = fabsf(W2[ch]);
            bb[2 * m + e] = isk ? b1[ch] : 0.0f;
        }

    __syncthreads();   // sW/sR dead; sT may alias now

    #pragma unroll
    for (int ii = 0; ii < 4; ii++) {
        #pragma unroll
        for (int m = 0; m < 4; m++) {
            float lo = __uint_as_float((uint)(acc[ii][m] & 0xffffffffu));
            float hi = __uint_as_float((uint)(acc[ii][m] >> 32));
            float o0 = gg[2 * m]     * (lo + bb[2 * m]);
            float o1 = gg[2 * m + 1] * (hi + bb[2 * m + 1]);
            ull pr = (ull)__float_as_uint(o0) | ((ull)__float_as_uint(o1) << 32);
            sT[(ti * 4 + ii) * 65 + tc + 16 * m] = pr;
        }
    }
    __syncthreads();

    // coalesced pair-major writeout
    ull* dst = (isk ? g_ksp : g_qsp) + (size_t)bh * NP * T;
    for (int idx = tid; idx < 64 * NP; idx += 256) {
        int r = idx & 63, p = idx >> 6;
        dst[p * T + r0 + r] = sT[r * 65 + p];
    }
}

// ---------------- K3: pairwise relu main kernel ----------------
// R8 config (1024 thr, 64x256 tile) with split-half smem layout to kill kv bank conflicts.
// sq_lo/sq_hi: [64p][16 qgroups] 16B slots; sk_lo/sk_hi: [64p][64 kgroups] 16B slots.
constexpr int SM3_BYTES = 2048 * 8 * 2 + 8192 * 8 * 2 + NP * 8;   // 164352

__global__ __launch_bounds__(1024, 1) void k3_main(
    const float* __restrict__ W2, const float* __restrict__ b2,
    float* __restrict__ out)
{
    extern __shared__ ull sm3[];
    ull* sq_lo = sm3;                 // [p][g<16] rows 4g+0,1   (2048 ull)
    ull* sq_hi = sq_lo + 2048;        // [p][g<16] rows 4g+2,3
    ull* sk_lo = sq_hi + 2048;        // [p][g<64] cols 4g+0,1   (8192 ull)
    ull* sk_hi = sk_lo + 8192;        // [p][g<64] cols 4g+2,3
    ull* ssg   = sk_hi + 8192;        // [64] packed (+-1.0f, +-1.0f)

    int tid = threadIdx.x;
    int bx  = blockIdx.x;
    int bh  = bx >> 4;
    int it  = (bx >> 1) & 7;
    int jt  = bx & 1;
    int i0  = it * 64, j0 = jt * 256;

    const ull* gq = g_qsp + (size_t)bh * NP * T;
    const ull* gk = g_ksp + (size_t)bh * NP * T;

    // fills: gmem-coalesced reads; split-half smem writes (conflict-free)
    for (int idx = tid; idx < NP * 64; idx += 1024) {
        int p = idx >> 6, r = idx & 63;
        int g = r >> 2, h = (r >> 1) & 1, c = r & 1;
        (h ? sq_hi : sq_lo)[(p * 16 + g) * 2 + c] = gq[p * T + i0 + r];
    }
    for (int idx = tid; idx < NP * 256; idx += 1024) {
        int p = idx >> 8, j = idx & 255;
        int g = j >> 2, h = (j >> 1) & 1, c = j & 1;
        (h ? sk_hi : sk_lo)[(p * 64 + g) * 2 + c] = gk[p * T + j0 + j];
    }
    if (tid < NP) {
        uint s0 = 0x3F800000u | (__float_as_uint(W2[2 * tid])     & 0x80000000u);
        uint s1 = 0x3F800000u | (__float_as_uint(W2[2 * tid + 1]) & 0x80000000u);
        ssg[tid] = (ull)s0 | ((ull)s1 << 32);
    }
    __syncthreads();

    int warp = tid >> 5, lane = tid & 31;
    int wi = warp >> 3, wj = warp & 7;   // 4x8 warps: warp tile 16x32
    int li = lane >> 3, lj = lane & 7;   // lanes: 4 row-groups x 8 col-groups

    int qg = wi * 4 + li;                // q group (rows 4qg..4qg+3)
    int kg = wj * 8 + lj;                // k group (cols 4kg..4kg+3)

    const ull* qlo = sq_lo + qg * 2;     // + p*32
    const ull* qhi = sq_hi + qg * 2;
    const ull* klo = sk_lo + kg * 2;     // + p*128
    const ull* khi = sk_hi + kg * 2;

    ull acc[4][4];
    #pragma unroll
    for (int r = 0; r < 4; r++)
        #pragma unroll
        for (int s = 0; s < 4; s++) acc[r][s] = 0ull;

    #pragma unroll 1
    for (int p = 0; p < NP; p++) {
        ulonglong2 qv01 = *(const ulonglong2*)(qlo + p * 32);    // rows 4li+0,1
        ulonglong2 qv23 = *(const ulonglong2*)(qhi + p * 32);    // rows 4li+2,3
        ulonglong2 kv01 = *(const ulonglong2*)(klo + p * 128);   // cols 4lj+0,1
        ulonglong2 kv23 = *(const ulonglong2*)(khi + p * 128);   // cols 4lj+2,3
        ull qv[4] = { qv01.x, qv01.y, qv23.x, qv23.y };
        ull kv[4] = { kv01.x, kv01.y, kv23.x, kv23.y };
        ull sg = ssg[p];
        #pragma unroll
        for (int r = 0; r < 4; r++)
            #pragma unroll
            for (int s = 0; s < 4; s++) {
                // u = q+k (packed); relu halves (FMNMX, alu pipe); acc += u * (+-1) (packed)
                asm("{\n\t"
                    ".reg .b64 t;\n\t"
                    ".reg .f32 lo, hi;\n\t"
                    "add.rn.f32x2 t, %1, %2;\n\t"
                    "mov.b64 {lo, hi}, t;\n\t"
                    "max.f32 lo, lo, 0f00000000;\n\t"
                    "max.f32 hi, hi, 0f00000000;\n\t"
                    "mov.b64 t, {lo, hi};\n\t"
                    "fma.rn.f32x2 %0, t, %3, %0;\n\t"
                    "}"
                    : "+l"(acc[r][s]) : "l"(qv[r]), "l"(kv[s]), "l"(sg));
            }
    }

    float b2v = b2[0];
    // rows: i0 + 4*qg + r; cols: j0 + 4*kg + s (consecutive -> STG.128)
    float* ob = out + (size_t)(bh * T + i0 + 4 * qg) * T + j0 + 4 * kg;
    #pragma unroll
    for (int r = 0; r < 4; r++) {
        float4 v;
        float* vp = (float*)&v;
        #pragma unroll
        for (int s = 0; s < 4; s++) {
            float lo = __uint_as_float((uint)(acc[r][s] & 0xffffffffu));
            float hi = __uint_as_float((uint)(acc[r][s] >> 32));
            vp[s] = lo + hi + b2v;
        }
        *(float4*)(ob + (size_t)r * T) = v;
    }
}

// ---------------- launch ----------------
extern "C" void kernel_launch(void* const* d_in, const int* in_sizes, int n_in,
                              void* d_out, int out_size) {
    const float* q  = (const float*)d_in[0];
    const float* k  = (const float*)d_in[1];
    const float* W1 = (const float*)d_in[2];
    const float* b1 = (const float*)d_in[3];
    const float* W2 = (const float*)d_in[4];
    const float* b2 = (const float*)d_in[5];
    float* out = (float*)d_out;

    cudaFuncSetAttribute(k1_proj, cudaFuncAttributeMaxDynamicSharedMemorySize, SM1_BYTES);
    cudaFuncSetAttribute(k3_main, cudaFuncAttributeMaxDynamicSharedMemorySize, SM3_BYTES);

    k1_proj<<<dim3(8, BH, 2), 256, SM1_BYTES>>>(q, k, W1, b1, W2);
    k3_main<<<128, 1024, SM3_BYTES>>>(W2, b2, out);
}